// round 15
// baseline (speedup 1.0000x reference)
#include <cuda_runtime.h>
#include <cuda_fp16.h>
#include <cstdint>

// Problem constants (fixed dataset)
#define N_NODES 16384
#define EMB     500
#define EMBP    512
#define IN_SZ   4096
#define MAX_E   524288
#define NMASK   (N_NODES - 1)
#define MCHUNK  4096              // aggregate/decode pipeline chunk (nodes)

// ---------------- scratch (device globals) ----------------------------------
__device__ __align__(16) __half g_xh[(size_t)N_NODES * IN_SZ];
__device__ __align__(16) __half g_wench[EMBP * IN_SZ];
__device__ __align__(16) float  g_bencp[EMBP];
__device__ __align__(16) __half g_wdech[IN_SZ * EMBP];
__device__ __align__(16) __half g_hh[N_NODES * EMBP];
__device__ __align__(16) __half g_hgch[N_NODES * EMBP];
__device__ float g_dinv[N_NODES];
__device__ int   g_deg[N_NODES];
__device__ int   g_count[N_NODES];
__device__ int   g_off[N_NODES + 1];
__device__ int   g_cursor[N_NODES];
__device__ int   g_src[MAX_E];
__device__ int   g_bsum[16];

// ---------------- conversion prologue ---------------------------------------
__global__ void conv_x_kernel(const float4* __restrict__ x) {
    size_t base = (size_t)blockIdx.x * blockDim.x * 2 + threadIdx.x;
    __half2* d = (__half2*)g_xh;
#pragma unroll
    for (int j = 0; j < 2; j++) {
        size_t i = base + (size_t)j * blockDim.x;
        float4 v = __ldcs(x + i);
        d[i * 2]     = __floats2half2_rn(v.x, v.y);
        d[i * 2 + 1] = __floats2half2_rn(v.z, v.w);
    }
}

__global__ void conv_wenc_kernel(const float* __restrict__ wenc) {
    int q = blockIdx.x * blockDim.x + threadIdx.x;
    int row = q >> 10;
    int c4 = (q & 1023) * 4;
    __half2 h0, h1;
    if (row < EMB) {
        float4 v = *(const float4*)(wenc + (size_t)row * IN_SZ + c4);
        h0 = __floats2half2_rn(v.x, v.y);
        h1 = __floats2half2_rn(v.z, v.w);
    } else {
        h0 = __floats2half2_rn(0.f, 0.f);
        h1 = h0;
    }
    __half2* d = (__half2*)(g_wench + (size_t)row * IN_SZ + c4);
    d[0] = h0; d[1] = h1;
}

__global__ void conv_benc_kernel(const float* __restrict__ benc) {
    int i = blockIdx.x * blockDim.x + threadIdx.x;
    if (i < EMBP) g_bencp[i] = (i < EMB) ? benc[i] : 0.f;
}

__global__ void conv_wdec_kernel(const float* __restrict__ wdec) {
    int q = blockIdx.x * blockDim.x + threadIdx.x;
    int row = q >> 7;
    int c = (q & 127) * 4;
    __half2 h0, h1;
    if (c < EMB) {
        float4 v = *(const float4*)(wdec + (size_t)row * EMB + c);
        h0 = __floats2half2_rn(v.x, v.y);
        h1 = __floats2half2_rn(v.z, v.w);
    } else {
        h0 = __floats2half2_rn(0.f, 0.f);
        h1 = h0;
    }
    __half2* d = (__half2*)(g_wdech + (size_t)row * EMBP + c);
    d[0] = h0; d[1] = h1;
}

// ---------------- CSR build --------------------------------------------------
__global__ void zero_kernel() {
    int i = blockIdx.x * blockDim.x + threadIdx.x;
    if (i < 2 * N_NODES) {
        if (i < N_NODES) g_deg[i] = 0;
        else             g_count[i - N_NODES] = 0;
    }
}

__global__ void count_kernel(const int* __restrict__ ei, int E) {
    int e = blockIdx.x * blockDim.x + threadIdx.x;
    if (e < E) {
        atomicAdd(&g_deg[ei[e] & NMASK], 1);
        atomicAdd(&g_count[ei[E + e] & NMASK], 1);
    }
}

__global__ void scan1_kernel() {
    __shared__ int s[1024];
    int t = threadIdx.x;
    int i = blockIdx.x * 1024 + t;
    int v = g_count[i];
    s[t] = v;
    __syncthreads();
    for (int off = 1; off < 1024; off <<= 1) {
        int u = 0;
        if (t >= off) u = s[t - off];
        __syncthreads();
        if (t >= off) s[t] += u;
        __syncthreads();
    }
    g_off[i] = s[t] - v;
    if (t == 1023) g_bsum[blockIdx.x] = s[1023];
}

__global__ void scan23_kernel() {
    int i = blockIdx.x * blockDim.x + threadIdx.x;
    if (i < N_NODES) {
        int blk = i >> 10;
        int boff = 0;
        for (int k = 0; k < blk; k++) boff += g_bsum[k];
        int o = g_off[i] + boff;
        g_off[i] = o;
        g_cursor[i] = o;
        if (i == N_NODES - 1) g_off[N_NODES] = o + g_count[i];
        int d = g_deg[i];
        g_dinv[i] = (d > 0) ? rsqrtf((float)d) : 0.0f;
    }
}

__global__ void fill_kernel(const int* __restrict__ ei, int E) {
    int e = blockIdx.x * blockDim.x + threadIdx.x;
    if (e < E) {
        int col = ei[E + e] & NMASK;
        int slot = atomicAdd(&g_cursor[col], 1);
        g_src[slot < MAX_E ? slot : MAX_E - 1] = ei[e] & NMASK;
    }
}

// ---------------- GCN aggregate (2-edge unrolled; node-offset chunked) --------
__global__ __launch_bounds__(128)
void aggregate_kernel(const float* __restrict__ conv_weight, int node0) {
    int n = node0 + blockIdx.x;
    int t = threadIdx.x;
    float cw = conv_weight[0];
    float dn = g_dinv[n];
    int beg = g_off[n], end = g_off[n + 1];
    float a0 = 0.f, a1 = 0.f, a2 = 0.f, a3 = 0.f;
    float b0 = 0.f, b1 = 0.f, b2 = 0.f, b3 = 0.f;
    int e = beg;
    for (; e + 1 < end; e += 2) {
        int s0 = g_src[e], s1 = g_src[e + 1];
        float c0 = dn * g_dinv[s0] * cw;
        float c1 = dn * g_dinv[s1] * cw;
        uint2 r0 = *(const uint2*)(g_hh + (size_t)s0 * EMBP + t * 4);
        uint2 r1 = *(const uint2*)(g_hh + (size_t)s1 * EMBP + t * 4);
        float2 p00 = __half22float2(*(__half2*)&r0.x), p01 = __half22float2(*(__half2*)&r0.y);
        float2 p10 = __half22float2(*(__half2*)&r1.x), p11 = __half22float2(*(__half2*)&r1.y);
        a0 += c0 * p00.x; a1 += c0 * p00.y; a2 += c0 * p01.x; a3 += c0 * p01.y;
        b0 += c1 * p10.x; b1 += c1 * p10.y; b2 += c1 * p11.x; b3 += c1 * p11.y;
    }
    if (e < end) {
        int s0 = g_src[e];
        float c0 = dn * g_dinv[s0] * cw;
        uint2 r0 = *(const uint2*)(g_hh + (size_t)s0 * EMBP + t * 4);
        float2 p00 = __half22float2(*(__half2*)&r0.x), p01 = __half22float2(*(__half2*)&r0.y);
        a0 += c0 * p00.x; a1 += c0 * p00.y; a2 += c0 * p01.x; a3 += c0 * p01.y;
    }
    a0 += b0; a1 += b1; a2 += b2; a3 += b3;
    uint2 rs = *(const uint2*)(g_hh + (size_t)n * EMBP + t * 4);
    float2 q0 = __half22float2(*(__half2*)&rs.x), q1 = __half22float2(*(__half2*)&rs.y);
    __half2 o0 = __floats2half2_rn(a0 + q0.x, a1 + q0.y);
    __half2 o1 = __floats2half2_rn(a2 + q1.x, a3 + q1.y);
    uint2 w;
    w.x = *(uint32_t*)&o0; w.y = *(uint32_t*)&o1;
    *(uint2*)(g_hgch + (size_t)n * EMBP + t * 4) = w;
}

// ---------------- fp16 mma.sync GEMM: 128x128 tile, BK=64, 4 warps 64x64 ----
__device__ __forceinline__ void mma16816(float* c, const uint32_t* a, uint32_t b0, uint32_t b1) {
    asm volatile(
        "mma.sync.aligned.m16n8k16.row.col.f32.f16.f16.f32 "
        "{%0,%1,%2,%3}, {%4,%5,%6,%7}, {%8,%9}, {%0,%1,%2,%3};\n"
        : "+f"(c[0]), "+f"(c[1]), "+f"(c[2]), "+f"(c[3])
        : "r"(a[0]), "r"(a[1]), "r"(a[2]), "r"(a[3]), "r"(b0), "r"(b1));
}

__device__ __forceinline__ void ldsm4(uint32_t* r, uint32_t addr) {
    asm volatile("ldmatrix.sync.aligned.m8n8.x4.shared.b16 {%0,%1,%2,%3}, [%4];\n"
        : "=r"(r[0]), "=r"(r[1]), "=r"(r[2]), "=r"(r[3]) : "r"(addr));
}

__device__ __forceinline__ void cpasync16(uint32_t dst, const void* src) {
    asm volatile("cp.async.cg.shared.global [%0], [%1], 16;\n" :: "r"(dst), "l"(src));
}

#define PITCH    144
#define TILE_SZ  (128 * PITCH)            // 18432
#define STAGE_SZ (2 * TILE_SZ)            // 36864 (A + B)
#define SMEM_GEMM (3 * STAGE_SZ)          // 110592

// PHASE 0: encode  g_hh = sigmoid(g_xh @ g_wench^T + g_bencp)  [16384x512], K=4096
// PHASE 1: decode  out  = g_hgch @ g_wdech^T + bdec            [Mchunk x 4096], K=512
// m_base: row offset for decode chunking.
template <int PHASE>
__global__ __launch_bounds__(128, 2)
void gemm_async(const float* __restrict__ bias_in, float* __restrict__ Cout, int m_base) {
    constexpr int K   = (PHASE == 0) ? IN_SZ : EMBP;
    constexpr int LDA = (PHASE == 0) ? IN_SZ : EMBP;
    constexpr int LDB = (PHASE == 0) ? IN_SZ : EMBP;
    constexpr int LDC = (PHASE == 0) ? EMBP  : IN_SZ;
    constexpr int NC  = K / 64;
    const __half* A = (PHASE == 0) ? g_xh    : g_hgch;
    const __half* B = (PHASE == 0) ? g_wench : g_wdech;
    const float* bias = (PHASE == 0) ? g_bencp : bias_in;

    extern __shared__ __align__(16) char smem[];
    uint32_t sbase;
    asm("{ .reg .u64 t; cvta.to.shared.u64 t, %1; cvt.u32.u64 %0, t; }" : "=r"(sbase) : "l"(smem));

    int tid = threadIdx.x;
    int m0 = m_base + blockIdx.y * 128;
    int n0 = blockIdx.x * 128;
    int lane = tid & 31, wid = tid >> 5;
    int wm = wid & 1, wn = wid >> 1;   // 2x2 warps; warp tile 64(m) x 64(n)

    int quad = lane >> 3, rin = lane & 7;
    uint32_t offA = (uint32_t)((wm * 64 + (quad & 1) * 8 + rin) * PITCH + (quad >> 1) * 16);
    uint32_t offB = (uint32_t)((wn * 64 + ((lane >> 4) & 1) * 8 + rin) * PITCH + ((lane >> 3) & 1) * 16);

    float acc[4][8][4];
#pragma unroll
    for (int mt = 0; mt < 4; mt++)
#pragma unroll
        for (int nt = 0; nt < 8; nt++)
#pragma unroll
            for (int i = 0; i < 4; i++) acc[mt][nt][i] = 0.f;

    auto load_stage = [&](int st, int k0) {
        uint32_t ba = sbase + st * STAGE_SZ;
        uint32_t bb = ba + TILE_SZ;
#pragma unroll
        for (int j = 0; j < 8; j++) {
            int idx = tid + j * 128;
            int r = idx >> 3, cc = idx & 7;
            cpasync16(ba + r * PITCH + cc * 16, A + (size_t)(m0 + r) * LDA + k0 + cc * 8);
            cpasync16(bb + r * PITCH + cc * 16, B + (size_t)(n0 + r) * LDB + k0 + cc * 8);
        }
    };

    load_stage(0, 0);
    asm volatile("cp.async.commit_group;\n");
    if (NC > 1) {
        load_stage(1, 64);
        asm volatile("cp.async.commit_group;\n");
    }

    for (int i = 0; i < NC; i++) {
        if (i + 2 < NC) {
            load_stage((i + 2) % 3, (i + 2) * 64);
            asm volatile("cp.async.commit_group;\n");
            asm volatile("cp.async.wait_group 2;\n");
        } else if (i + 1 < NC) {
            asm volatile("cp.async.wait_group 1;\n");
        } else {
            asm volatile("cp.async.wait_group 0;\n");
        }
        __syncthreads();

        uint32_t baseA = sbase + (i % 3) * STAGE_SZ + offA;
        uint32_t baseB = sbase + (i % 3) * STAGE_SZ + TILE_SZ + offB;

        uint32_t af[2][4][4], bf[2][4][4];
#pragma unroll
        for (int mt = 0; mt < 4; mt++)
            ldsm4(af[0][mt], baseA + mt * (16 * PITCH));
#pragma unroll
        for (int ntp = 0; ntp < 4; ntp++)
            ldsm4(bf[0][ntp], baseB + ntp * (16 * PITCH));

#pragma unroll
        for (int s = 0; s < 4; s++) {
            int cur = s & 1, nxt = cur ^ 1;
            if (s < 3) {
#pragma unroll
                for (int mt = 0; mt < 4; mt++)
                    ldsm4(af[nxt][mt], baseA + mt * (16 * PITCH) + (s + 1) * 32);
#pragma unroll
                for (int ntp = 0; ntp < 4; ntp++)
                    ldsm4(bf[nxt][ntp], baseB + ntp * (16 * PITCH) + (s + 1) * 32);
            }
#pragma unroll
            for (int mt = 0; mt < 4; mt++) {
#pragma unroll
                for (int nt = 0; nt < 8; nt++)
                    mma16816(acc[mt][nt], af[cur][mt],
                             bf[cur][nt >> 1][(nt & 1) * 2], bf[cur][nt >> 1][(nt & 1) * 2 + 1]);
            }
        }
        __syncthreads();
    }

    int g = lane >> 2, c = lane & 3;
#pragma unroll
    for (int mt = 0; mt < 4; mt++) {
#pragma unroll
        for (int nt = 0; nt < 8; nt++) {
            int n = n0 + wn * 64 + nt * 8 + c * 2;
            float b0 = bias[n], b1 = bias[n + 1];
#pragma unroll
            for (int hr = 0; hr < 2; hr++) {
                int m = m0 + wm * 64 + mt * 16 + g + hr * 8;
                float v0 = acc[mt][nt][hr * 2 + 0] + b0;
                float v1 = acc[mt][nt][hr * 2 + 1] + b1;
                if (PHASE == 0) {
                    v0 = 1.0f / (1.0f + __expf(-v0));
                    v1 = 1.0f / (1.0f + __expf(-v1));
                    *(__half2*)(g_hh + (size_t)m * LDC + n) = __floats2half2_rn(v0, v1);
                } else {
                    *(float2*)(Cout + (size_t)m * LDC + n) = make_float2(v0, v1);
                }
            }
        }
    }
}

// ---------------- launch: forked capture + agg/decode pipeline ---------------
extern "C" void kernel_launch(void* const* d_in, const int* in_sizes, int n_in,
                              void* d_out, int out_size) {
    const float* x    = (const float*)d_in[0];
    const int*   ei   = (const int*)d_in[1];
    const float* wenc = (const float*)d_in[2];
    const float* benc = (const float*)d_in[3];
    const float* wdec = (const float*)d_in[4];
    const float* bdec = (const float*)d_in[5];
    const float* cw   = (const float*)d_in[6];
    float*       out  = (float*)d_out;

    int E = in_sizes[1] / 2;

    cudaFuncSetAttribute(gemm_async<0>, cudaFuncAttributeMaxDynamicSharedMemorySize, SMEM_GEMM);
    cudaFuncSetAttribute(gemm_async<1>, cudaFuncAttributeMaxDynamicSharedMemorySize, SMEM_GEMM);

    cudaStream_t s1, s2;
    cudaStreamCreateWithFlags(&s1, cudaStreamNonBlocking);
    cudaStreamCreateWithFlags(&s2, cudaStreamNonBlocking);
    cudaEvent_t evF, evW, evEnc;
    cudaEventCreateWithFlags(&evF, cudaEventDisableTiming);
    cudaEventCreateWithFlags(&evW, cudaEventDisableTiming);
    cudaEventCreateWithFlags(&evEnc, cudaEventDisableTiming);
    cudaEvent_t evAgg[4];
    for (int c = 0; c < 4; c++) cudaEventCreateWithFlags(&evAgg[c], cudaEventDisableTiming);

    cudaEventRecord(evF, 0);
    cudaStreamWaitEvent(s1, evF, 0);
    cudaStreamWaitEvent(s2, evF, 0);

    conv_x_kernel<<<(N_NODES * (IN_SZ / 4)) / (256 * 2), 256>>>((const float4*)x);

    // s2: encode weight/bias converts (overlap conv_x)
    conv_wenc_kernel<<<(EMBP * IN_SZ / 4) / 256, 256, 0, s2>>>(wenc);
    conv_benc_kernel<<<2, 256, 0, s2>>>(benc);
    cudaEventRecord(evW, s2);

    // s1: wdec convert + CSR build (independent of encode)
    conv_wdec_kernel<<<(IN_SZ * EMBP / 4) / 256, 256, 0, s1>>>(wdec);
    zero_kernel<<<(2 * N_NODES + 511) / 512, 512, 0, s1>>>();
    count_kernel<<<(E + 255) / 256, 256, 0, s1>>>(ei, E);
    scan1_kernel<<<16, 1024, 0, s1>>>();
    scan23_kernel<<<32, 512, 0, s1>>>();
    fill_kernel<<<(E + 255) / 256, 256, 0, s1>>>(ei, E);

    // encode on main stream (after conv_x implicit + s2 weights)
    cudaStreamWaitEvent(0, evW, 0);
    {
        dim3 grid(EMBP / 128, N_NODES / 128);
        gemm_async<0><<<grid, 128, SMEM_GEMM>>>(nullptr, nullptr, 0);
    }
    cudaEventRecord(evEnc, 0);

    // s1: aggregate in 4 node-chunks (each needs full encode + CSR)
    cudaStreamWaitEvent(s1, evEnc, 0);
    for (int c = 0; c < 4; c++) {
        aggregate_kernel<<<MCHUNK, 128, 0, s1>>>(cw, c * MCHUNK);
        cudaEventRecord(evAgg[c], s1);
    }

    // main: decode in 4 M-chunks, each gated only on its aggregate chunk
    for (int c = 0; c < 4; c++) {
        cudaStreamWaitEvent(0, evAgg[c], 0);
        dim3 grid(IN_SZ / 128, MCHUNK / 128);
        gemm_async<1><<<grid, 128, SMEM_GEMM>>>(bdec, out, c * MCHUNK);
    }

    cudaStreamDestroy(s1);
    cudaStreamDestroy(s2);
    cudaEventDestroy(evF);
    cudaEventDestroy(evW);
    cudaEventDestroy(evEnc);
    for (int c = 0; c < 4; c++) cudaEventDestroy(evAgg[c]);
}

// round 16
// speedup vs baseline: 1.1505x; 1.1505x over previous
#include <cuda_runtime.h>
#include <cuda_fp16.h>
#include <cstdint>

// Problem constants (fixed dataset)
#define N_NODES 16384
#define EMB     500
#define EMBP    512
#define IN_SZ   4096
#define MAX_E   524288
#define NMASK   (N_NODES - 1)

// ---------------- scratch (device globals) ----------------------------------
__device__ __align__(16) __half g_wench[EMBP * IN_SZ];
__device__ __align__(16) float  g_bencp[EMBP];
__device__ __align__(16) __half g_wdech[IN_SZ * EMBP];
__device__ __align__(16) __half g_hh[N_NODES * EMBP];
__device__ __align__(16) __half g_hgch[N_NODES * EMBP];
__device__ float g_dinv[N_NODES];
__device__ int   g_deg[N_NODES];
__device__ int   g_count[N_NODES];
__device__ int   g_off[N_NODES + 1];
__device__ int   g_cursor[N_NODES];
__device__ int   g_src[MAX_E];
__device__ int   g_bsum[16];

// ---------------- conversion prologue ---------------------------------------
__global__ void conv_wenc_kernel(const float* __restrict__ wenc) {
    int q = blockIdx.x * blockDim.x + threadIdx.x;
    int row = q >> 10;
    int c4 = (q & 1023) * 4;
    __half2 h0, h1;
    if (row < EMB) {
        float4 v = *(const float4*)(wenc + (size_t)row * IN_SZ + c4);
        h0 = __floats2half2_rn(v.x, v.y);
        h1 = __floats2half2_rn(v.z, v.w);
    } else {
        h0 = __floats2half2_rn(0.f, 0.f);
        h1 = h0;
    }
    __half2* d = (__half2*)(g_wench + (size_t)row * IN_SZ + c4);
    d[0] = h0; d[1] = h1;
}

__global__ void conv_benc_kernel(const float* __restrict__ benc) {
    int i = blockIdx.x * blockDim.x + threadIdx.x;
    if (i < EMBP) g_bencp[i] = (i < EMB) ? benc[i] : 0.f;
}

__global__ void conv_wdec_kernel(const float* __restrict__ wdec) {
    int q = blockIdx.x * blockDim.x + threadIdx.x;
    int row = q >> 7;
    int c = (q & 127) * 4;
    __half2 h0, h1;
    if (c < EMB) {
        float4 v = *(const float4*)(wdec + (size_t)row * EMB + c);
        h0 = __floats2half2_rn(v.x, v.y);
        h1 = __floats2half2_rn(v.z, v.w);
    } else {
        h0 = __floats2half2_rn(0.f, 0.f);
        h1 = h0;
    }
    __half2* d = (__half2*)(g_wdech + (size_t)row * EMBP + c);
    d[0] = h0; d[1] = h1;
}

// ---------------- CSR build --------------------------------------------------
__global__ void zero_kernel() {
    int i = blockIdx.x * blockDim.x + threadIdx.x;
    if (i < 2 * N_NODES) {
        if (i < N_NODES) g_deg[i] = 0;
        else             g_count[i - N_NODES] = 0;
    }
}

__global__ void count_kernel(const int* __restrict__ ei, int E) {
    int e = blockIdx.x * blockDim.x + threadIdx.x;
    if (e < E) {
        atomicAdd(&g_deg[ei[e] & NMASK], 1);
        atomicAdd(&g_count[ei[E + e] & NMASK], 1);
    }
}

__global__ void scan1_kernel() {
    __shared__ int s[1024];
    int t = threadIdx.x;
    int i = blockIdx.x * 1024 + t;
    int v = g_count[i];
    s[t] = v;
    __syncthreads();
    for (int off = 1; off < 1024; off <<= 1) {
        int u = 0;
        if (t >= off) u = s[t - off];
        __syncthreads();
        if (t >= off) s[t] += u;
        __syncthreads();
    }
    g_off[i] = s[t] - v;
    if (t == 1023) g_bsum[blockIdx.x] = s[1023];
}

__global__ void scan23_kernel() {
    int i = blockIdx.x * blockDim.x + threadIdx.x;
    if (i < N_NODES) {
        int blk = i >> 10;
        int boff = 0;
        for (int k = 0; k < blk; k++) boff += g_bsum[k];
        int o = g_off[i] + boff;
        g_off[i] = o;
        g_cursor[i] = o;
        if (i == N_NODES - 1) g_off[N_NODES] = o + g_count[i];
        int d = g_deg[i];
        g_dinv[i] = (d > 0) ? rsqrtf((float)d) : 0.0f;
    }
}

__global__ void fill_kernel(const int* __restrict__ ei, int E) {
    int e = blockIdx.x * blockDim.x + threadIdx.x;
    if (e < E) {
        int col = ei[E + e] & NMASK;
        int slot = atomicAdd(&g_cursor[col], 1);
        g_src[slot < MAX_E ? slot : MAX_E - 1] = ei[e] & NMASK;
    }
}

// ---------------- GCN aggregate (2-edge unrolled) -----------------------------
__global__ __launch_bounds__(128)
void aggregate_kernel(const float* __restrict__ conv_weight) {
    int n = blockIdx.x;
    int t = threadIdx.x;
    float cw = conv_weight[0];
    float dn = g_dinv[n];
    int beg = g_off[n], end = g_off[n + 1];
    float a0 = 0.f, a1 = 0.f, a2 = 0.f, a3 = 0.f;
    float b0 = 0.f, b1 = 0.f, b2 = 0.f, b3 = 0.f;
    int e = beg;
    for (; e + 1 < end; e += 2) {
        int s0 = g_src[e], s1 = g_src[e + 1];
        float c0 = dn * g_dinv[s0] * cw;
        float c1 = dn * g_dinv[s1] * cw;
        uint2 r0 = *(const uint2*)(g_hh + (size_t)s0 * EMBP + t * 4);
        uint2 r1 = *(const uint2*)(g_hh + (size_t)s1 * EMBP + t * 4);
        float2 p00 = __half22float2(*(__half2*)&r0.x), p01 = __half22float2(*(__half2*)&r0.y);
        float2 p10 = __half22float2(*(__half2*)&r1.x), p11 = __half22float2(*(__half2*)&r1.y);
        a0 += c0 * p00.x; a1 += c0 * p00.y; a2 += c0 * p01.x; a3 += c0 * p01.y;
        b0 += c1 * p10.x; b1 += c1 * p10.y; b2 += c1 * p11.x; b3 += c1 * p11.y;
    }
    if (e < end) {
        int s0 = g_src[e];
        float c0 = dn * g_dinv[s0] * cw;
        uint2 r0 = *(const uint2*)(g_hh + (size_t)s0 * EMBP + t * 4);
        float2 p00 = __half22float2(*(__half2*)&r0.x), p01 = __half22float2(*(__half2*)&r0.y);
        a0 += c0 * p00.x; a1 += c0 * p00.y; a2 += c0 * p01.x; a3 += c0 * p01.y;
    }
    a0 += b0; a1 += b1; a2 += b2; a3 += b3;
    uint2 rs = *(const uint2*)(g_hh + (size_t)n * EMBP + t * 4);
    float2 q0 = __half22float2(*(__half2*)&rs.x), q1 = __half22float2(*(__half2*)&rs.y);
    __half2 o0 = __floats2half2_rn(a0 + q0.x, a1 + q0.y);
    __half2 o1 = __floats2half2_rn(a2 + q1.x, a3 + q1.y);
    uint2 w;
    w.x = *(uint32_t*)&o0; w.y = *(uint32_t*)&o1;
    *(uint2*)(g_hgch + (size_t)n * EMBP + t * 4) = w;
}

// ---------------- mma helpers -------------------------------------------------
__device__ __forceinline__ void mma16816(float* c, const uint32_t* a, uint32_t b0, uint32_t b1) {
    asm volatile(
        "mma.sync.aligned.m16n8k16.row.col.f32.f16.f16.f32 "
        "{%0,%1,%2,%3}, {%4,%5,%6,%7}, {%8,%9}, {%0,%1,%2,%3};\n"
        : "+f"(c[0]), "+f"(c[1]), "+f"(c[2]), "+f"(c[3])
        : "r"(a[0]), "r"(a[1]), "r"(a[2]), "r"(a[3]), "r"(b0), "r"(b1));
}

__device__ __forceinline__ void ldsm4(uint32_t* r, uint32_t addr) {
    asm volatile("ldmatrix.sync.aligned.m8n8.x4.shared.b16 {%0,%1,%2,%3}, [%4];\n"
        : "=r"(r[0]), "=r"(r[1]), "=r"(r[2]), "=r"(r[3]) : "r"(addr));
}

__device__ __forceinline__ void cpasync16(uint32_t dst, const void* src) {
    asm volatile("cp.async.cg.shared.global [%0], [%1], 16;\n" :: "r"(dst), "l"(src));
}

// ---------------- encode GEMM: fused fp32-A, 128x128 tile, BK=64 -------------
// g_hh = sigmoid(x_fp32 @ g_wench^T + g_bencp)  [16384x512], K=4096
// A staged as raw fp32 (pitch 288B, conflict-free LDS.64), converted in-register.
#define PITCH_A32 288
#define A32_TILE  (128 * PITCH_A32)        // 36864
#define PITCH     144
#define B16_TILE  (128 * PITCH)            // 18432
#define ENC_STAGE (A32_TILE + B16_TILE)    // 55296
#define SMEM_ENC  (2 * ENC_STAGE)          // 110592

__global__ __launch_bounds__(128, 2)
void gemm_enc(const float* __restrict__ X) {
    constexpr int NC = IN_SZ / 64;         // 64 chunks
    const __half* B = g_wench;

    extern __shared__ __align__(16) char smem[];
    uint32_t sbase;
    asm("{ .reg .u64 t; cvta.to.shared.u64 t, %1; cvt.u32.u64 %0, t; }" : "=r"(sbase) : "l"(smem));

    int tid = threadIdx.x;
    int m0 = blockIdx.y * 128;
    int n0 = blockIdx.x * 128;
    int lane = tid & 31, wid = tid >> 5;
    int wm = wid & 1, wn = wid >> 1;       // 2x2 warps; warp tile 64x64

    int g = lane >> 2, c = lane & 3;
    int rin = lane & 7;
    uint32_t offB = (uint32_t)((wn * 64 + ((lane >> 4) & 1) * 8 + rin) * PITCH + ((lane >> 3) & 1) * 16);

    float acc[4][8][4];
#pragma unroll
    for (int mt = 0; mt < 4; mt++)
#pragma unroll
        for (int nt = 0; nt < 8; nt++)
#pragma unroll
            for (int i = 0; i < 4; i++) acc[mt][nt][i] = 0.f;

    auto load_stage = [&](int st, int k0) {
        uint32_t ba = sbase + st * ENC_STAGE;
        uint32_t bb = ba + A32_TILE;
        // A: 128 rows x 64 floats = 2048 16B chunks
#pragma unroll
        for (int j = 0; j < 16; j++) {
            int idx = tid + j * 128;
            int r = idx >> 4, cc = idx & 15;
            cpasync16(ba + r * PITCH_A32 + cc * 16, X + (size_t)(m0 + r) * IN_SZ + k0 + cc * 4);
        }
        // B: 128 rows x 64 halfs = 1024 16B chunks
#pragma unroll
        for (int j = 0; j < 8; j++) {
            int idx = tid + j * 128;
            int r = idx >> 3, cc = idx & 7;
            cpasync16(bb + r * PITCH + cc * 16, B + (size_t)(n0 + r) * IN_SZ + k0 + cc * 8);
        }
    };

    load_stage(0, 0);
    asm volatile("cp.async.commit_group;\n");

    for (int i = 0; i < NC; i++) {
        if (i + 1 < NC) {
            load_stage((i + 1) & 1, (i + 1) * 64);
            asm volatile("cp.async.commit_group;\n");
            asm volatile("cp.async.wait_group 1;\n");
        } else {
            asm volatile("cp.async.wait_group 0;\n");
        }
        __syncthreads();

        int st = i & 1;
        const char* sA = smem + st * ENC_STAGE;
        uint32_t baseB = sbase + st * ENC_STAGE + A32_TILE + offB;

#pragma unroll
        for (int ks = 0; ks < 64; ks += 16) {
            uint32_t bf[4][4];
#pragma unroll
            for (int ntp = 0; ntp < 4; ntp++)
                ldsm4(bf[ntp], baseB + ntp * (16 * PITCH) + ks * 2);

            uint32_t af[4][4];
#pragma unroll
            for (int mt = 0; mt < 4; mt++) {
                int r0 = wm * 64 + mt * 16 + g;
                const char* pr0 = sA + r0 * PITCH_A32;
                const char* pr8 = pr0 + 8 * PITCH_A32;
                int col0 = (ks + 2 * c) * 4;
                float2 v0 = *(const float2*)(pr0 + col0);
                float2 v1 = *(const float2*)(pr8 + col0);
                float2 v2 = *(const float2*)(pr0 + col0 + 32);
                float2 v3 = *(const float2*)(pr8 + col0 + 32);
                __half2 h0 = __floats2half2_rn(v0.x, v0.y);
                __half2 h1 = __floats2half2_rn(v1.x, v1.y);
                __half2 h2 = __floats2half2_rn(v2.x, v2.y);
                __half2 h3 = __floats2half2_rn(v3.x, v3.y);
                af[mt][0] = *(uint32_t*)&h0;
                af[mt][1] = *(uint32_t*)&h1;
                af[mt][2] = *(uint32_t*)&h2;
                af[mt][3] = *(uint32_t*)&h3;
            }
#pragma unroll
            for (int mt = 0; mt < 4; mt++) {
#pragma unroll
                for (int nt = 0; nt < 8; nt++)
                    mma16816(acc[mt][nt], af[mt],
                             bf[nt >> 1][(nt & 1) * 2], bf[nt >> 1][(nt & 1) * 2 + 1]);
            }
        }
        __syncthreads();
    }

    // epilogue: bias + sigmoid -> fp16 g_hh
#pragma unroll
    for (int mt = 0; mt < 4; mt++) {
#pragma unroll
        for (int nt = 0; nt < 8; nt++) {
            int n = n0 + wn * 64 + nt * 8 + c * 2;
            float b0 = g_bencp[n], b1 = g_bencp[n + 1];
#pragma unroll
            for (int hr = 0; hr < 2; hr++) {
                int m = m0 + wm * 64 + mt * 16 + g + hr * 8;
                float v0 = acc[mt][nt][hr * 2 + 0] + b0;
                float v1 = acc[mt][nt][hr * 2 + 1] + b1;
                v0 = 1.0f / (1.0f + __expf(-v0));
                v1 = 1.0f / (1.0f + __expf(-v1));
                *(__half2*)(g_hh + (size_t)m * EMBP + n) = __floats2half2_rn(v0, v1);
            }
        }
    }
}

// ---------------- decode GEMM: fp16 3-stage (unchanged from R13) -------------
#define TILE_SZ  (128 * PITCH)            // 18432
#define STAGE_SZ (2 * TILE_SZ)            // 36864
#define SMEM_DEC (3 * STAGE_SZ)           // 110592

__global__ __launch_bounds__(128, 2)
void gemm_dec(const float* __restrict__ bias, float* __restrict__ Cout) {
    constexpr int NC = EMBP / 64;
    const __half* A = g_hgch;
    const __half* B = g_wdech;

    extern __shared__ __align__(16) char smem[];
    uint32_t sbase;
    asm("{ .reg .u64 t; cvta.to.shared.u64 t, %1; cvt.u32.u64 %0, t; }" : "=r"(sbase) : "l"(smem));

    int tid = threadIdx.x;
    int m0 = blockIdx.y * 128;
    int n0 = blockIdx.x * 128;
    int lane = tid & 31, wid = tid >> 5;
    int wm = wid & 1, wn = wid >> 1;

    int quad = lane >> 3, rin = lane & 7;
    uint32_t offA = (uint32_t)((wm * 64 + (quad & 1) * 8 + rin) * PITCH + (quad >> 1) * 16);
    uint32_t offB = (uint32_t)((wn * 64 + ((lane >> 4) & 1) * 8 + rin) * PITCH + ((lane >> 3) & 1) * 16);

    float acc[4][8][4];
#pragma unroll
    for (int mt = 0; mt < 4; mt++)
#pragma unroll
        for (int nt = 0; nt < 8; nt++)
#pragma unroll
            for (int i = 0; i < 4; i++) acc[mt][nt][i] = 0.f;

    auto load_stage = [&](int st, int k0) {
        uint32_t ba = sbase + st * STAGE_SZ;
        uint32_t bb = ba + TILE_SZ;
#pragma unroll
        for (int j = 0; j < 8; j++) {
            int idx = tid + j * 128;
            int r = idx >> 3, cc = idx & 7;
            cpasync16(ba + r * PITCH + cc * 16, A + (size_t)(m0 + r) * EMBP + k0 + cc * 8);
            cpasync16(bb + r * PITCH + cc * 16, B + (size_t)(n0 + r) * EMBP + k0 + cc * 8);
        }
    };

    load_stage(0, 0);
    asm volatile("cp.async.commit_group;\n");
    load_stage(1, 64);
    asm volatile("cp.async.commit_group;\n");

    for (int i = 0; i < NC; i++) {
        if (i + 2 < NC) {
            load_stage((i + 2) % 3, (i + 2) * 64);
            asm volatile("cp.async.commit_group;\n");
            asm volatile("cp.async.wait_group 2;\n");
        } else if (i + 1 < NC) {
            asm volatile("cp.async.wait_group 1;\n");
        } else {
            asm volatile("cp.async.wait_group 0;\n");
        }
        __syncthreads();

        uint32_t baseA = sbase + (i % 3) * STAGE_SZ + offA;
        uint32_t baseB = sbase + (i % 3) * STAGE_SZ + TILE_SZ + offB;

        uint32_t af[2][4][4], bf[2][4][4];
#pragma unroll
        for (int mt = 0; mt < 4; mt++)
            ldsm4(af[0][mt], baseA + mt * (16 * PITCH));
#pragma unroll
        for (int ntp = 0; ntp < 4; ntp++)
            ldsm4(bf[0][ntp], baseB + ntp * (16 * PITCH));

#pragma unroll
        for (int s = 0; s < 4; s++) {
            int cur = s & 1, nxt = cur ^ 1;
            if (s < 3) {
#pragma unroll
                for (int mt = 0; mt < 4; mt++)
                    ldsm4(af[nxt][mt], baseA + mt * (16 * PITCH) + (s + 1) * 32);
#pragma unroll
                for (int ntp = 0; ntp < 4; ntp++)
                    ldsm4(bf[nxt][ntp], baseB + ntp * (16 * PITCH) + (s + 1) * 32);
            }
#pragma unroll
            for (int mt = 0; mt < 4; mt++) {
#pragma unroll
                for (int nt = 0; nt < 8; nt++)
                    mma16816(acc[mt][nt], af[cur][mt],
                             bf[cur][nt >> 1][(nt & 1) * 2], bf[cur][nt >> 1][(nt & 1) * 2 + 1]);
            }
        }
        __syncthreads();
    }

    int g = lane >> 2, c = lane & 3;
#pragma unroll
    for (int mt = 0; mt < 4; mt++) {
#pragma unroll
        for (int nt = 0; nt < 8; nt++) {
            int n = n0 + wn * 64 + nt * 8 + c * 2;
            float b0 = bias[n], b1 = bias[n + 1];
#pragma unroll
            for (int hr = 0; hr < 2; hr++) {
                int m = m0 + wm * 64 + mt * 16 + g + hr * 8;
                float v0 = acc[mt][nt][hr * 2 + 0] + b0;
                float v1 = acc[mt][nt][hr * 2 + 1] + b1;
                *(float2*)(Cout + (size_t)m * IN_SZ + n) = make_float2(v0, v1);
            }
        }
    }
}

// ---------------- launch: R13 fork structure, conv_x eliminated --------------
extern "C" void kernel_launch(void* const* d_in, const int* in_sizes, int n_in,
                              void* d_out, int out_size) {
    const float* x    = (const float*)d_in[0];
    const int*   ei   = (const int*)d_in[1];
    const float* wenc = (const float*)d_in[2];
    const float* benc = (const float*)d_in[3];
    const float* wdec = (const float*)d_in[4];
    const float* bdec = (const float*)d_in[5];
    const float* cw   = (const float*)d_in[6];
    float*       out  = (float*)d_out;

    int E = in_sizes[1] / 2;

    cudaFuncSetAttribute(gemm_enc, cudaFuncAttributeMaxDynamicSharedMemorySize, SMEM_ENC);
    cudaFuncSetAttribute(gemm_dec, cudaFuncAttributeMaxDynamicSharedMemorySize, SMEM_DEC);

    cudaStream_t s1;
    cudaStreamCreateWithFlags(&s1, cudaStreamNonBlocking);
    cudaEvent_t evF, evJ;
    cudaEventCreateWithFlags(&evF, cudaEventDisableTiming);
    cudaEventCreateWithFlags(&evJ, cudaEventDisableTiming);

    cudaEventRecord(evF, 0);
    cudaStreamWaitEvent(s1, evF, 0);

    // main: wenc/benc converts feed encode directly (no conv_x anymore)
    conv_wenc_kernel<<<(EMBP * IN_SZ / 4) / 256, 256>>>(wenc);
    conv_benc_kernel<<<2, 256>>>(benc);

    // s1: wdec convert + CSR build (independent of encode)
    conv_wdec_kernel<<<(IN_SZ * EMBP / 4) / 256, 256, 0, s1>>>(wdec);
    zero_kernel<<<(2 * N_NODES + 511) / 512, 512, 0, s1>>>();
    count_kernel<<<(E + 255) / 256, 256, 0, s1>>>(ei, E);
    scan1_kernel<<<16, 1024, 0, s1>>>();
    scan23_kernel<<<32, 512, 0, s1>>>();
    fill_kernel<<<(E + 255) / 256, 256, 0, s1>>>(ei, E);
    cudaEventRecord(evJ, s1);

    // encode: reads x fp32 directly
    {
        dim3 grid(EMBP / 128, N_NODES / 128);
        gemm_enc<<<grid, 128, SMEM_ENC>>>(x);
    }

    // join: aggregate needs encode (main) + CSR (s1)
    cudaStreamWaitEvent(0, evJ, 0);
    aggregate_kernel<<<N_NODES, 128>>>(cw);

    // decode
    {
        dim3 grid(IN_SZ / 128, N_NODES / 128);
        gemm_dec<<<grid, 128, SMEM_DEC>>>(bdec, out);
    }

    cudaStreamDestroy(s1);
    cudaEventDestroy(evF);
    cudaEventDestroy(evJ);
}